// round 16
// baseline (speedup 1.0000x reference)
#include <cuda_runtime.h>
#include <cstdint>

#define TMAX 1280

__device__ int g_lab[TMAX];        // fallback path only
__device__ float4 g_txyxy[TMAX];   // fallback path only
__device__ float2 g_tal[TMAX];     // fallback path only

__device__ __forceinline__ float frcp(float x) {
    float r;
    asm("rcp.approx.f32 %0, %1;" : "=f"(r) : "f"(x));
    return r;
}

// Packed f32x2 helpers (bit-exact per-lane .rn arithmetic; sm_100a).
#define PACK2(dst, lo, hi) \
    asm("mov.b64 %0, {%1, %2};" : "=l"(dst) : "r"(__float_as_uint(lo)), "r"(__float_as_uint(hi)))
#define UNPACK2(lo, hi, src) do { unsigned int _ulo, _uhi; \
    asm("mov.b64 {%0, %1}, %2;" : "=r"(_ulo), "=r"(_uhi) : "l"(src)); \
    lo = __uint_as_float(_ulo); hi = __uint_as_float(_uhi); } while (0)
#define ADDX2(dst, a, b) \
    asm("add.rn.f32x2 %0, %1, %2;" : "=l"(dst) : "l"(a), "l"(b))
#define FMAX2(dst, a, b, c) \
    asm("fma.rn.f32x2 %0, %1, %2, %3;" : "=l"(dst) : "l"(a), "l"(b), "l"(c))

// Fallback-path setup: label normalize + target xyxy/area precompute.
__global__ void setup_kernel(const float4* __restrict__ tboxes,
                             const int* __restrict__ lraw, int m) {
    __shared__ int is64;
    if (threadIdx.x == 0) is64 = 1;
    __syncthreads();
    for (int t = threadIdx.x; t < m / 2; t += blockDim.x)
        if (lraw[2 * t + 1] != 0) is64 = 0;
    __syncthreads();
    int f = is64;
    for (int j = threadIdx.x; j < m; j += blockDim.x) {
        int lab = f ? lraw[2 * j] : lraw[j];
        g_lab[j] = lab;
        float4 b = tboxes[j];
        float hw = 0.5f * b.z, hh = 0.5f * b.w;
        float4 t;
        t.x = b.x - hw; t.y = b.y - hh;
        t.z = b.x + hw; t.w = b.y + hh;
        g_txyxy[j] = t;
        float2 al;
        al.x = (t.z - t.x) * (t.w - t.y);
        al.y = __int_as_float(lab);
        g_tal[j] = al;
    }
}

// ---------------------------------------------------------------------------
// Fast-path tile body: 2 rows x 5 column steps (one column-quarter) per
// thread; R14 min/max-free formulation, unchanged math.
// Templated on label stride (SH=1: int64 source, SH=0: int32).
// ---------------------------------------------------------------------------
template <int SH>
__device__ __forceinline__ void cost_tile2(
    const float2* __restrict__ ssc2,     // smem (2-score) pairs for this 2-row group
    float* __restrict__ op,              // out + row0*M + colbase + tx
    const float4* __restrict__ tb,       // tboxes + colbase + tx
    const int* __restrict__ lp,          // lraw + ((colbase + tx) << SH)
    const unsigned long long nq0[2],     // packed (-qx0, -qy0)
    const unsigned long long nq1[2],     // packed (-qx1, -qy1)
    const float hqwx[2], const float hqwy[2],  // qw/2, qh/2
    const float qa[2])                   // qw*qh
{
    constexpr int M = 1280;

    unsigned long long PH, NH;
    PACK2(PH, 0.5f, 0.5f);
    PACK2(NH, -0.5f, -0.5f);

#pragma unroll
    for (int jj = 0; jj < 5; jj++) {
        float4 b = __ldg(tb + jj * 64);          // target cxcywh
        int lab = __ldg(lp + ((jj * 64) << SH)); // immediate-offset label

        unsigned long long bxy, bwh, t0, t1;
        PACK2(bxy, b.x, b.y);
        PACK2(bwh, b.z, b.w);
        FMAX2(t0, bwh, NH, bxy);                 // (tx0, ty0)
        FMAX2(t1, bwh, PH, bxy);                 // (tx1, ty1)
        float ta = b.z * b.w;
        float htwx = 0.5f * b.z, htwy = 0.5f * b.w;

        float2 sc2 = ssc2[lab];                  // one LDS.64: (2-sc) for both rows
        float scv[2] = {sc2.x, sc2.y};

#pragma unroll
        for (int k = 0; k < 2; k++) {
            unsigned long long d0, d1, sA2;
            ADDX2(d0, t0, nq0[k]);               // (tx0-qx0, ty0-qy0)
            ADDX2(d1, t1, nq1[k]);               // (tx1-qx1, ty1-qy1)
            ADDX2(sA2, d0, d1);                  // 2*(tc - qc) per dim

            float d0x, d0y, d1x, d1y, sax, say;
            UNPACK2(d0x, d0y, d0);
            UNPACK2(d1x, d1y, d1);
            UNPACK2(sax, say, sA2);

            float ax = fabsf(d1x) + fabsf(d0x);
            float ay = fabsf(d1y) + fabsf(d0y);
            float sAs = fabsf(sax) + fabsf(say); // 2*(|dcx|+|dcy|)

            float hswx = hqwx[k] + htwx;         // (qw+tw)/2
            float hswy = hqwy[k] + htwy;
            float vx = hqwx[k] - htwx;           // (qw-tw)/2
            float vy = hqwy[k] - htwy;
            float sB = fabsf(vx) + fabsf(vy);    // (|dw|+|dh|)/2

            float ox = fmaf(ax, -0.5f, hswx);    // min(hi)-max(lo), signed
            float oy = fmaf(ay, -0.5f, hswy);
            float ewx = fmaf(ax, 0.5f, hswx);    // enclosing span
            float ewy = fmaf(ay, 0.5f, hswy);

            float iw = fmaxf(ox, 0.0f), ih = fmaxf(oy, 0.0f);
            float inter = iw * ih;
            float ae = ewx * ewy;
            float uni = (qa[k] + ta) - inter;

            float s = fmaf(uni, frcp(ae), inter * frcp(uni));
            float c = fmaf(sAs, 2.5f, scv[k]);   // 5 * (|dcx|+|dcy|)
            c = fmaf(sB, 10.0f, c);              // 5 * (|dw|+|dh|)
            c = fmaf(-2.0f, s, c);

            op[k * M + jj * 64] = c;
        }
    }
}

// ---------------------------------------------------------------------------
// Fast path: C=91, M=1280, rows % 8 == 0. Single launch.
// QUARTER-TILE grid vs R14: each block covers 8 rows x 320 cols, so
// grid = (rows/8)*4 = 4800. 4800 quanta over 740 block-slots (5/SM x 148)
// -> ceil(6.49)=7 sub-waves -> makespan 1.75T vs R14's 2.0T (1200/740 -> 2).
// Block = 4 groups x (2 rows x 64 lanes); launch_bounds(256,5) -> 48 regs.
// ---------------------------------------------------------------------------
__global__ void __launch_bounds__(256, 5)
cost_kernel_fast(const float* __restrict__ scores,
                 const float4* __restrict__ boxes,
                 const int* __restrict__ lraw,
                 const float4* __restrict__ tboxes,
                 float* __restrict__ out) {
    constexpr int C = 91;
    constexpr int M = 1280;

    __shared__ float s_sc[4 * C * 2];   // [group][col][row-in-pair]
    __shared__ int s_is64;

    int tid = threadIdx.x;
    int tx = tid & 63;
    int ty = tid >> 6;
    int rb = blockIdx.x >> 2;           // row-block (8 rows)
    int cq = blockIdx.x & 3;            // column quarter (320 cols)
    int row0 = rb * 8 + ty * 2;
    int colbase = cq * 320;

    if (tid == 0) s_is64 = 1;
    __syncthreads();

    // Label-width probe: int64 labels (<2^31) have all-zero high words.
    {
        int any = 0;
#pragma unroll 1
        for (int t = tid; t < M / 2; t += 256)
            any |= lraw[2 * t + 1];
        if (any != 0) s_is64 = 0;
    }

    // Stage 8 score rows pre-negated and row-pair interleaved.
    {
        int w = tid >> 5, l = tid & 31;
        int g = w >> 1, r = w & 1;
        const float* src = scores + (size_t)(rb * 8 + g * 2 + r) * C;
#pragma unroll
        for (int c = l; c < C; c += 32)
            s_sc[g * (C * 2) + c * 2 + r] = 2.0f - __ldg(src + c);
    }

    unsigned long long nq0[2], nq1[2];
    float hqwx[2], hqwy[2], qa[2];
#pragma unroll
    for (int k = 0; k < 2; k++) {
        float4 bb = __ldg(boxes + row0 + k);
        float hw = 0.5f * bb.z, hh = 0.5f * bb.w;
        float qx0 = bb.x - hw, qy0 = bb.y - hh;
        float qx1 = bb.x + hw, qy1 = bb.y + hh;
        PACK2(nq0[k], -qx0, -qy0);
        PACK2(nq1[k], -qx1, -qy1);
        hqwx[k] = hw; hqwy[k] = hh;
        qa[k] = bb.z * bb.w;
    }
    __syncthreads();

    const float2* ssc2 = reinterpret_cast<const float2*>(s_sc + ty * (C * 2));
    float* op = out + (size_t)row0 * M + colbase + tx;
    const float4* tb = tboxes + colbase + tx;

    if (s_is64)
        cost_tile2<1>(ssc2, op, tb, lraw + 2 * (colbase + tx),
                      nq0, nq1, hqwx, hqwy, qa);
    else
        cost_tile2<0>(ssc2, op, tb, lraw + colbase + tx,
                      nq0, nq1, hqwx, hqwy, qa);
}

// ---------------------------------------------------------------------------
// Generic fallback for unexpected shapes.
// ---------------------------------------------------------------------------
__global__ void __launch_bounds__(256)
cost_kernel(const float* __restrict__ scores,
            const float4* __restrict__ boxes,
            const float4* __restrict__ tboxes,
            float* __restrict__ out,
            int rows, int C, int m) {
    int tid = threadIdx.x;
    int tx = tid & 63;
    int ty = tid >> 6;
    int row0 = blockIdx.x * 16 + ty * 4;

    float qcx[4], qcy[4], qw[4], qh[4];
    float qx0[4], qy0[4], qx1[4], qy1[4], qa[4];
    const float* srow[4];
    float* orow[4];

#pragma unroll
    for (int k = 0; k < 4; k++) {
        int r = row0 + k;
        if (r > rows - 1) r = rows - 1;
        float4 bb = __ldg(boxes + r);
        qcx[k] = bb.x; qcy[k] = bb.y; qw[k] = bb.z; qh[k] = bb.w;
        float hw = 0.5f * bb.z, hh = 0.5f * bb.w;
        qx0[k] = bb.x - hw; qy0[k] = bb.y - hh;
        qx1[k] = bb.x + hw; qy1[k] = bb.y + hh;
        qa[k] = (qx1[k] - qx0[k]) * (qy1[k] - qy0[k]);
        srow[k] = scores + (size_t)r * C;
        orow[k] = out + (size_t)r * m + tx;
    }

    int nj = (m + 63) >> 6;
    for (int jj = 0; jj < nj; jj++) {
        int j = tx + (jj << 6);
        if (j >= m) break;
        float4 t  = __ldg(g_txyxy + j);
        float4 tc = __ldg(tboxes + j);
        float2 al = __ldg(g_tal + j);
        float ta = al.x;
        int lab = __float_as_int(al.y);

#pragma unroll
        for (int k = 0; k < 4; k++) {
            float sc = __ldg(srow[k] + lab);
            float l1 = fabsf(qcx[k] - tc.x) + fabsf(qcy[k] - tc.y)
                     + fabsf(qw[k] - tc.z) + fabsf(qh[k] - tc.w);
            float ltx = fmaxf(qx0[k], t.x), lty = fmaxf(qy0[k], t.y);
            float rbx = fminf(qx1[k], t.z), rby = fminf(qy1[k], t.w);
            float iw = fmaxf(rbx - ltx, 0.0f), ih = fmaxf(rby - lty, 0.0f);
            float inter = iw * ih;
            float uni = qa[k] + ta - inter;
            float ex0 = fminf(qx0[k], t.x), ey0 = fminf(qy0[k], t.y);
            float ex1 = fmaxf(qx1[k], t.z), ey1 = fmaxf(qy1[k], t.w);
            float ae = (ex1 - ex0) * (ey1 - ey0);
            float s = fmaf(uni, frcp(ae), inter * frcp(uni));
            float c = fmaf(5.0f, l1, 2.0f - sc);
            c = fmaf(-2.0f, s, c);
            orow[k][(size_t)(jj << 6)] = c;
        }
    }
}

extern "C" void kernel_launch(void* const* d_in, const int* in_sizes, int n_in,
                              void* d_out, int out_size) {
    const float* scores  = (const float*)d_in[0];
    const float4* boxes  = (const float4*)d_in[1];
    const int*   labraw  = (const int*)d_in[2];
    const float4* tboxes = (const float4*)d_in[3];
    float* out = (float*)d_out;

    int rows = in_sizes[1] / 4;      // b*n = 9600
    int m    = in_sizes[3] / 4;      // 1280
    int C    = in_sizes[0] / rows;   // 91

    if (C == 91 && m == 1280 && (rows % 8) == 0) {
        cost_kernel_fast<<<(rows / 8) * 4, 256>>>(scores, boxes, labraw, tboxes, out);
    } else {
        setup_kernel<<<1, 512>>>(tboxes, labraw, m);
        int blocks = (rows + 15) / 16;
        cost_kernel<<<blocks, 256>>>(scores, boxes, tboxes, out, rows, C, m);
    }
}

// round 17
// speedup vs baseline: 1.0877x; 1.0877x over previous
#include <cuda_runtime.h>
#include <cstdint>

#define TMAX 1280

__device__ int g_lab[TMAX];        // fallback path only
__device__ float4 g_txyxy[TMAX];   // fallback path only
__device__ float2 g_tal[TMAX];     // fallback path only

__device__ __forceinline__ float frcp(float x) {
    float r;
    asm("rcp.approx.f32 %0, %1;" : "=f"(r) : "f"(x));
    return r;
}

// Packed f32x2 helpers (bit-exact per-lane .rn arithmetic; sm_100a).
#define PACK2(dst, lo, hi) \
    asm("mov.b64 %0, {%1, %2};" : "=l"(dst) : "r"(__float_as_uint(lo)), "r"(__float_as_uint(hi)))
#define UNPACK2(lo, hi, src) do { unsigned int _ulo, _uhi; \
    asm("mov.b64 {%0, %1}, %2;" : "=r"(_ulo), "=r"(_uhi) : "l"(src)); \
    lo = __uint_as_float(_ulo); hi = __uint_as_float(_uhi); } while (0)
#define ADDX2(dst, a, b) \
    asm("add.rn.f32x2 %0, %1, %2;" : "=l"(dst) : "l"(a), "l"(b))
#define FMAX2(dst, a, b, c) \
    asm("fma.rn.f32x2 %0, %1, %2, %3;" : "=l"(dst) : "l"(a), "l"(b), "l"(c))

// Fallback-path setup: label normalize + target xyxy/area precompute.
__global__ void setup_kernel(const float4* __restrict__ tboxes,
                             const int* __restrict__ lraw, int m) {
    __shared__ int is64;
    if (threadIdx.x == 0) is64 = 1;
    __syncthreads();
    for (int t = threadIdx.x; t < m / 2; t += blockDim.x)
        if (lraw[2 * t + 1] != 0) is64 = 0;
    __syncthreads();
    int f = is64;
    for (int j = threadIdx.x; j < m; j += blockDim.x) {
        int lab = f ? lraw[2 * j] : lraw[j];
        g_lab[j] = lab;
        float4 b = tboxes[j];
        float hw = 0.5f * b.z, hh = 0.5f * b.w;
        float4 t;
        t.x = b.x - hw; t.y = b.y - hh;
        t.z = b.x + hw; t.w = b.y + hh;
        g_txyxy[j] = t;
        float2 al;
        al.x = (t.z - t.x) * (t.w - t.y);
        al.y = __int_as_float(lab);
        g_tal[j] = al;
    }
}

// ---------------------------------------------------------------------------
// Fast-path tile body: 2 rows x 5 column steps (one column-quarter) per
// thread; R14 min/max-free packed formulation. Scores gathered directly
// from global (L1/L2-resident; R12 measured global ~= staged).
// Templated on label stride (SH=1: int64 source, SH=0: int32).
// ---------------------------------------------------------------------------
template <int SH>
__device__ __forceinline__ void cost_tile2(
    const float* __restrict__ sp,        // scores + row0*C
    float* __restrict__ op,              // out + row0*M + colbase + tx
    const float4* __restrict__ tb,       // tboxes + colbase + tx
    const int* __restrict__ lp,          // lraw + ((colbase + tx) << SH)
    const unsigned long long nq0[2],     // packed (-qx0, -qy0)
    const unsigned long long nq1[2],     // packed (-qx1, -qy1)
    const float hqwx[2], const float hqwy[2],  // qw/2, qh/2
    const float qa[2])                   // qw*qh
{
    constexpr int C = 91;
    constexpr int M = 1280;

    unsigned long long PH, NH;
    PACK2(PH, 0.5f, 0.5f);
    PACK2(NH, -0.5f, -0.5f);

#pragma unroll
    for (int jj = 0; jj < 5; jj++) {
        float4 b = __ldg(tb + jj * 64);          // target cxcywh
        int lab = __ldg(lp + ((jj * 64) << SH)); // immediate-offset label

        unsigned long long bxy, bwh, t0, t1;
        PACK2(bxy, b.x, b.y);
        PACK2(bwh, b.z, b.w);
        FMAX2(t0, bwh, NH, bxy);                 // (tx0, ty0)
        FMAX2(t1, bwh, PH, bxy);                 // (tx1, ty1)
        float ta = b.z * b.w;
        float htwx = 0.5f * b.z, htwy = 0.5f * b.w;

        const float* sa = sp + lab;
        float scv[2];
#pragma unroll
        for (int k = 0; k < 2; k++) scv[k] = __ldg(sa + k * C);

#pragma unroll
        for (int k = 0; k < 2; k++) {
            unsigned long long d0, d1, sA2;
            ADDX2(d0, t0, nq0[k]);               // (tx0-qx0, ty0-qy0)
            ADDX2(d1, t1, nq1[k]);               // (tx1-qx1, ty1-qy1)
            ADDX2(sA2, d0, d1);                  // 2*(tc - qc) per dim

            float d0x, d0y, d1x, d1y, sax, say;
            UNPACK2(d0x, d0y, d0);
            UNPACK2(d1x, d1y, d1);
            UNPACK2(sax, say, sA2);

            float ax = fabsf(d1x) + fabsf(d0x);
            float ay = fabsf(d1y) + fabsf(d0y);
            float sAs = fabsf(sax) + fabsf(say); // 2*(|dcx|+|dcy|)

            float hswx = hqwx[k] + htwx;         // (qw+tw)/2
            float hswy = hqwy[k] + htwy;
            float vx = hqwx[k] - htwx;           // (qw-tw)/2
            float vy = hqwy[k] - htwy;
            float sB = fabsf(vx) + fabsf(vy);    // (|dw|+|dh|)/2

            float ox = fmaf(ax, -0.5f, hswx);    // min(hi)-max(lo), signed
            float oy = fmaf(ay, -0.5f, hswy);
            float ewx = fmaf(ax, 0.5f, hswx);    // enclosing span
            float ewy = fmaf(ay, 0.5f, hswy);

            float iw = fmaxf(ox, 0.0f), ih = fmaxf(oy, 0.0f);
            float inter = iw * ih;
            float ae = ewx * ewy;
            float uni = (qa[k] + ta) - inter;

            float s = fmaf(uni, frcp(ae), inter * frcp(uni));
            float c = fmaf(sAs, 2.5f, 2.0f - scv[k]);  // 5*(|dcx|+|dcy|) + (2-sc)
            c = fmaf(sB, 10.0f, c);              // 5 * (|dw|+|dh|)
            c = fmaf(-2.0f, s, c);

            op[k * M + jj * 64] = c;
        }
    }
}

// ---------------------------------------------------------------------------
// Fast path: C=91, M=1280, rows % 8 == 0. Single launch.
// Quarter-tile grid (8 rows x 320 cols, grid=4800) for the fine wave tail
// (ceil(6.49)=7 sub-waves -> 1.079x makespan vs 1.23x at grid=1200), with
// the R15 startup overhead stripped: NO smem staging, 64-word label probe
// reduced via __syncthreads_or (one barrier, zero shared memory).
// Block = 4 groups x (2 rows x 64 lanes); launch_bounds(256,5) -> 51-reg cap.
// ---------------------------------------------------------------------------
__global__ void __launch_bounds__(256, 5)
cost_kernel_fast(const float* __restrict__ scores,
                 const float4* __restrict__ boxes,
                 const int* __restrict__ lraw,
                 const float4* __restrict__ tboxes,
                 float* __restrict__ out) {
    constexpr int C = 91;
    constexpr int M = 1280;

    int tid = threadIdx.x;
    int tx = tid & 63;
    int ty = tid >> 6;
    int rb = blockIdx.x >> 2;           // row-block (8 rows)
    int cq = blockIdx.x & 3;            // column quarter (320 cols)
    int row0 = rb * 8 + ty * 2;
    int colbase = cq * 320;

    // Label-width probe: 64 odd words (int64 labels < 2^31 -> all zero;
    // int32 random labels all-zero w.p. (1/91)^64 ~ 0).
    int any = (tid < 64) ? lraw[2 * tid + 1] : 0;

    unsigned long long nq0[2], nq1[2];
    float hqwx[2], hqwy[2], qa[2];
#pragma unroll
    for (int k = 0; k < 2; k++) {
        float4 bb = __ldg(boxes + row0 + k);
        float hw = 0.5f * bb.z, hh = 0.5f * bb.w;
        float qx0 = bb.x - hw, qy0 = bb.y - hh;
        float qx1 = bb.x + hw, qy1 = bb.y + hh;
        PACK2(nq0[k], -qx0, -qy0);
        PACK2(nq1[k], -qx1, -qy1);
        hqwx[k] = hw; hqwy[k] = hh;
        qa[k] = bb.z * bb.w;
    }

    int is64 = !__syncthreads_or(any);  // single barrier; no smem

    const float* sp = scores + row0 * C;
    float* op = out + (size_t)row0 * M + colbase + tx;
    const float4* tb = tboxes + colbase + tx;

    if (is64)
        cost_tile2<1>(sp, op, tb, lraw + 2 * (colbase + tx),
                      nq0, nq1, hqwx, hqwy, qa);
    else
        cost_tile2<0>(sp, op, tb, lraw + colbase + tx,
                      nq0, nq1, hqwx, hqwy, qa);
}

// ---------------------------------------------------------------------------
// Generic fallback for unexpected shapes.
// ---------------------------------------------------------------------------
__global__ void __launch_bounds__(256)
cost_kernel(const float* __restrict__ scores,
            const float4* __restrict__ boxes,
            const float4* __restrict__ tboxes,
            float* __restrict__ out,
            int rows, int C, int m) {
    int tid = threadIdx.x;
    int tx = tid & 63;
    int ty = tid >> 6;
    int row0 = blockIdx.x * 16 + ty * 4;

    float qcx[4], qcy[4], qw[4], qh[4];
    float qx0[4], qy0[4], qx1[4], qy1[4], qa[4];
    const float* srow[4];
    float* orow[4];

#pragma unroll
    for (int k = 0; k < 4; k++) {
        int r = row0 + k;
        if (r > rows - 1) r = rows - 1;
        float4 bb = __ldg(boxes + r);
        qcx[k] = bb.x; qcy[k] = bb.y; qw[k] = bb.z; qh[k] = bb.w;
        float hw = 0.5f * bb.z, hh = 0.5f * bb.w;
        qx0[k] = bb.x - hw; qy0[k] = bb.y - hh;
        qx1[k] = bb.x + hw; qy1[k] = bb.y + hh;
        qa[k] = (qx1[k] - qx0[k]) * (qy1[k] - qy0[k]);
        srow[k] = scores + (size_t)r * C;
        orow[k] = out + (size_t)r * m + tx;
    }

    int nj = (m + 63) >> 6;
    for (int jj = 0; jj < nj; jj++) {
        int j = tx + (jj << 6);
        if (j >= m) break;
        float4 t  = __ldg(g_txyxy + j);
        float4 tc = __ldg(tboxes + j);
        float2 al = __ldg(g_tal + j);
        float ta = al.x;
        int lab = __float_as_int(al.y);

#pragma unroll
        for (int k = 0; k < 4; k++) {
            float sc = __ldg(srow[k] + lab);
            float l1 = fabsf(qcx[k] - tc.x) + fabsf(qcy[k] - tc.y)
                     + fabsf(qw[k] - tc.z) + fabsf(qh[k] - tc.w);
            float ltx = fmaxf(qx0[k], t.x), lty = fmaxf(qy0[k], t.y);
            float rbx = fminf(qx1[k], t.z), rby = fminf(qy1[k], t.w);
            float iw = fmaxf(rbx - ltx, 0.0f), ih = fmaxf(rby - lty, 0.0f);
            float inter = iw * ih;
            float uni = qa[k] + ta - inter;
            float ex0 = fminf(qx0[k], t.x), ey0 = fminf(qy0[k], t.y);
            float ex1 = fmaxf(qx1[k], t.z), ey1 = fmaxf(qy1[k], t.w);
            float ae = (ex1 - ex0) * (ey1 - ey0);
            float s = fmaf(uni, frcp(ae), inter * frcp(uni));
            float c = fmaf(5.0f, l1, 2.0f - sc);
            c = fmaf(-2.0f, s, c);
            orow[k][(size_t)(jj << 6)] = c;
        }
    }
}

extern "C" void kernel_launch(void* const* d_in, const int* in_sizes, int n_in,
                              void* d_out, int out_size) {
    const float* scores  = (const float*)d_in[0];
    const float4* boxes  = (const float4*)d_in[1];
    const int*   labraw  = (const int*)d_in[2];
    const float4* tboxes = (const float4*)d_in[3];
    float* out = (float*)d_out;

    int rows = in_sizes[1] / 4;      // b*n = 9600
    int m    = in_sizes[3] / 4;      // 1280
    int C    = in_sizes[0] / rows;   // 91

    if (C == 91 && m == 1280 && (rows % 8) == 0) {
        cost_kernel_fast<<<(rows / 8) * 4, 256>>>(scores, boxes, labraw, tboxes, out);
    } else {
        setup_kernel<<<1, 512>>>(tboxes, labraw, m);
        int blocks = (rows + 15) / 16;
        cost_kernel<<<blocks, 256>>>(scores, boxes, tboxes, out, rows, C, m);
    }
}